// round 9
// baseline (speedup 1.0000x reference)
#include <cuda_runtime.h>
#include <cuda_fp16.h>

#define NMAX 100000
#define EMAX 1600000
#define CMAX 128

// Scratch (__device__ globals: allocation-free rule)
__device__ __half d_G[(size_t)NMAX * CMAX];       // messages (half)
__device__ __half d_B1[(size_t)NMAX * CMAX];      // activations (half)
__device__ __half d_B2[(size_t)NMAX * CMAX];
__device__ float  d_dinv[NMAX];
__device__ int    d_cnt[NMAX];
__device__ int    d_cur[NMAX];
__device__ int    d_off[NMAX + 1];
__device__ int    d_csr[EMAX];
__device__ int    d_blk[128];
__device__ int    d_blk2[128];
__device__ unsigned d_gmin[64];

#define FMA2(d, a, b, c) \
    asm("fma.rn.f32x2 %0, %1, %2, %3;" : "=l"(d) : "l"(a), "l"(b), "l"(c))
#define PACK2(d, x) \
    asm("mov.b64 %0, {%1, %1};" : "=l"(d) : "f"(x))
#define UNPACK2(lo, hi, v) \
    asm("mov.b64 {%0, %1}, %2;" : "=f"(lo), "=f"(hi) : "l"(v))

__device__ __forceinline__ unsigned enc_f(float f) {
    unsigned u = __float_as_uint(f);
    return (u & 0x80000000u) ? ~u : (u | 0x80000000u);
}
__device__ __forceinline__ float dec_f(unsigned e) {
    unsigned u = (e & 0x80000000u) ? (e ^ 0x80000000u) : ~e;
    return __uint_as_float(u);
}

// A-tile loaders (fp32 input x, or half activations)
__device__ __forceinline__ float4 loadA4(const float* A, size_t row, int k4) {
    return __ldg((const float4*)(A + row * 128) + k4);
}
__device__ __forceinline__ float4 loadA4(const __half* A, size_t row, int k4) {
    uint2 u = __ldg((const uint2*)(A + row * 128) + k4);
    float2 f0 = __half22float2(*(__half2*)&u.x);
    float2 f1 = __half22float2(*(__half2*)&u.y);
    return make_float4(f0.x, f0.y, f1.x, f1.y);
}

// ================= degree histogram =================
__global__ void k_hist(const int* __restrict__ dst, int E) {
    int i = blockIdx.x * blockDim.x + threadIdx.x;
    if (i < E) atomicAdd(&d_cnt[dst[i]], 1);
}

// ================= CSR scans =================
__global__ void k_scan1(int N) {
    __shared__ int sh[256];
    int t = threadIdx.x;
    int base = blockIdx.x * 1024 + t * 4;
    int c0 = 0, c1 = 0, c2 = 0, c3 = 0;
    if (base + 3 < N) {
        int4 v = *(const int4*)&d_cnt[base];
        c0 = v.x; c1 = v.y; c2 = v.z; c3 = v.w;
    } else {
        if (base + 0 < N) c0 = d_cnt[base + 0];
        if (base + 1 < N) c1 = d_cnt[base + 1];
        if (base + 2 < N) c2 = d_cnt[base + 2];
        if (base + 3 < N) c3 = d_cnt[base + 3];
    }
    int s = c0 + c1 + c2 + c3;
    sh[t] = s;
    __syncthreads();
    for (int d = 1; d < 256; d <<= 1) {
        int v = (t >= d) ? sh[t - d] : 0;
        __syncthreads();
        sh[t] += v;
        __syncthreads();
    }
    int excl = sh[t] - s;
    if (base + 0 < N) d_off[base + 0] = excl;
    if (base + 1 < N) d_off[base + 1] = excl + c0;
    if (base + 2 < N) d_off[base + 2] = excl + c0 + c1;
    if (base + 3 < N) d_off[base + 3] = excl + c0 + c1 + c2;
    if (t == 255) d_blk[blockIdx.x] = sh[255];
}

__global__ void k_scan2(int nblk) {
    __shared__ int sh[128];
    int t = threadIdx.x;
    int v = (t < nblk) ? d_blk[t] : 0;
    sh[t] = v;
    __syncthreads();
    for (int d = 1; d < 128; d <<= 1) {
        int u = (t >= d) ? sh[t - d] : 0;
        __syncthreads();
        sh[t] += u;
        __syncthreads();
    }
    d_blk2[t] = sh[t] - v;
}

// Also: computes dinv, zeroes d_cnt/d_cur for graph replay, inits gmin.
__global__ void k_scan3(int N, int E) {
    int i = blockIdx.x * blockDim.x + threadIdx.x;
    if (i < N) {
        d_off[i] += d_blk2[i >> 10];
        d_dinv[i] = rsqrtf((float)d_cnt[i] + 1.0f);  // +1 self-loop
        d_cnt[i] = 0;                                 // self-clean for replay
        d_cur[i] = 0;
    }
    if (i == 0) d_off[N] = E;
    if (blockIdx.x == 0 && threadIdx.x < 64) d_gmin[threadIdx.x] = 0xFFFFFFFFu;
}

// ================= GEMM: g[row] = half(dinv[row] * (A[row] @ W)) =================
// 128 threads; each computes an 8x8 tile via fma.rn.f32x2.
// FILL: blocks with bid < fillBlocks do the CSR fill instead (low bids start
// in the first wave, overlapping the GEMM; scan3 already ran).
template <int COLS, int TROWS, bool FILL, typename AT>
__global__ void __launch_bounds__(128)
k_gemm(const AT* __restrict__ A, const float* __restrict__ W,
       __half* __restrict__ g, int N,
       const int* __restrict__ src, const int* __restrict__ dstp, int E, int fillBlocks)
{
    if (FILL && (int)blockIdx.x < fillBlocks) {
        for (int i = blockIdx.x * 128 + threadIdx.x; i < E; i += fillBlocks * 128) {
            int d = dstp[i];
            int p = atomicAdd(&d_cur[d], 1);
            d_csr[d_off[d] + p] = src[i];
        }
        return;
    }
    extern __shared__ float sm[];
    constexpr int RS = TROWS + 4;
    float* Xs = sm;               // [128][RS] transposed (k-major, row-fast)
    float* Ws = sm + 128 * RS;    // [128][COLS]
    constexpr int CG = COLS / 8;
    const int tid = threadIdx.x;
    const int cg = tid % CG;
    const int rg = tid / CG;
    const int base = (blockIdx.x - (FILL ? fillBlocks : 0)) * TROWS;

    for (int i = tid; i < 128 * COLS / 4; i += 128)
        ((float4*)Ws)[i] = __ldg((const float4*)W + i);

    for (int i = tid; i < TROWS * 32; i += 128) {
        int r = i % TROWS;
        int k4 = i / TROWS;
        int row = base + r;
        float4 v = make_float4(0.f, 0.f, 0.f, 0.f);
        if (row < N) v = loadA4(A, (size_t)row, k4);
        int k = k4 * 4;
        Xs[(k + 0) * RS + r] = v.x;
        Xs[(k + 1) * RS + r] = v.y;
        Xs[(k + 2) * RS + r] = v.z;
        Xs[(k + 3) * RS + r] = v.w;
    }
    __syncthreads();

    unsigned long long acc[8][4];
#pragma unroll
    for (int r = 0; r < 8; r++)
#pragma unroll
        for (int c = 0; c < 4; c++) acc[r][c] = 0ull;

#pragma unroll 4
    for (int k = 0; k < 128; k++) {
        float4 xa = *(const float4*)&Xs[k * RS + rg * 8];
        float4 xb = *(const float4*)&Xs[k * RS + rg * 8 + 4];
        float xr[8] = {xa.x, xa.y, xa.z, xa.w, xb.x, xb.y, xb.z, xb.w};
        unsigned long long x2[8];
#pragma unroll
        for (int r = 0; r < 8; r++) PACK2(x2[r], xr[r]);
        ulonglong2 wA = *(const ulonglong2*)&Ws[k * COLS + cg * 8];
        ulonglong2 wB = *(const ulonglong2*)&Ws[k * COLS + cg * 8 + 4];
        unsigned long long w2[4] = {wA.x, wA.y, wB.x, wB.y};
#pragma unroll
        for (int r = 0; r < 8; r++)
#pragma unroll
            for (int c = 0; c < 4; c++) FMA2(acc[r][c], x2[r], w2[c], acc[r][c]);
    }

#pragma unroll
    for (int r = 0; r < 8; r++) {
        int row = base + rg * 8 + r;
        if (row < N) {
            float dv = d_dinv[row];
            __half2 h[4];
#pragma unroll
            for (int c = 0; c < 4; c++) {
                float lo, hi;
                UNPACK2(lo, hi, acc[r][c]);
                h[c] = __floats2half2_rn(lo * dv, hi * dv);
            }
            *(uint4*)(g + (size_t)row * COLS + cg * 8) = *(uint4*)h;
        }
    }
}

// ================= CSR aggregate (half msgs, fp32 accum, 1 warp/node) ============
// 8-deep software pipeline: 8 row loads in flight while the NEXT 8 indices load.
__device__ __forceinline__ void acc_u2(float& a0, float& a1, float& a2, float& a3, uint2 v) {
    float2 f0 = __half22float2(*(__half2*)&v.x);
    float2 f1 = __half22float2(*(__half2*)&v.y);
    a0 += f0.x; a1 += f0.y; a2 += f1.x; a3 += f1.y;
}

__global__ void k_agg128(const __half* __restrict__ g, const float* __restrict__ bias,
                         __half* __restrict__ out, int N)
{
    int node = (blockIdx.x * blockDim.x + threadIdx.x) >> 5;
    int lane = threadIdx.x & 31;
    if (node >= N) return;
    const uint2* gp = (const uint2*)g;

    float a0 = 0.f, a1 = 0.f, a2 = 0.f, a3 = 0.f;
    acc_u2(a0, a1, a2, a3, __ldg(&gp[(size_t)node * 32 + lane]));   // self-loop
    int s = d_off[node], e = d_off[node + 1];
    int j = s;
    int c0, c1, c2, c3, c4, c5, c6, c7;
    bool have = (j + 8 <= e);
    if (have) {
        c0 = __ldg(d_csr + j);     c1 = __ldg(d_csr + j + 1);
        c2 = __ldg(d_csr + j + 2); c3 = __ldg(d_csr + j + 3);
        c4 = __ldg(d_csr + j + 4); c5 = __ldg(d_csr + j + 5);
        c6 = __ldg(d_csr + j + 6); c7 = __ldg(d_csr + j + 7);
    }
    while (have) {
        bool nxt = (j + 16 <= e);
        int m0, m1, m2, m3, m4, m5, m6, m7;
        if (nxt) {
            m0 = __ldg(d_csr + j + 8);  m1 = __ldg(d_csr + j + 9);
            m2 = __ldg(d_csr + j + 10); m3 = __ldg(d_csr + j + 11);
            m4 = __ldg(d_csr + j + 12); m5 = __ldg(d_csr + j + 13);
            m6 = __ldg(d_csr + j + 14); m7 = __ldg(d_csr + j + 15);
        }
        uint2 v0 = __ldg(&gp[(size_t)c0 * 32 + lane]);
        uint2 v1 = __ldg(&gp[(size_t)c1 * 32 + lane]);
        uint2 v2 = __ldg(&gp[(size_t)c2 * 32 + lane]);
        uint2 v3 = __ldg(&gp[(size_t)c3 * 32 + lane]);
        uint2 v4 = __ldg(&gp[(size_t)c4 * 32 + lane]);
        uint2 v5 = __ldg(&gp[(size_t)c5 * 32 + lane]);
        uint2 v6 = __ldg(&gp[(size_t)c6 * 32 + lane]);
        uint2 v7 = __ldg(&gp[(size_t)c7 * 32 + lane]);
        acc_u2(a0, a1, a2, a3, v0); acc_u2(a0, a1, a2, a3, v1);
        acc_u2(a0, a1, a2, a3, v2); acc_u2(a0, a1, a2, a3, v3);
        acc_u2(a0, a1, a2, a3, v4); acc_u2(a0, a1, a2, a3, v5);
        acc_u2(a0, a1, a2, a3, v6); acc_u2(a0, a1, a2, a3, v7);
        c0 = m0; c1 = m1; c2 = m2; c3 = m3;
        c4 = m4; c5 = m5; c6 = m6; c7 = m7;
        j += 8;
        have = nxt;
    }
    if (j + 4 <= e) {
        int n0 = __ldg(d_csr + j),     n1 = __ldg(d_csr + j + 1);
        int n2 = __ldg(d_csr + j + 2), n3 = __ldg(d_csr + j + 3);
        uint2 v0 = __ldg(&gp[(size_t)n0 * 32 + lane]);
        uint2 v1 = __ldg(&gp[(size_t)n1 * 32 + lane]);
        uint2 v2 = __ldg(&gp[(size_t)n2 * 32 + lane]);
        uint2 v3 = __ldg(&gp[(size_t)n3 * 32 + lane]);
        acc_u2(a0, a1, a2, a3, v0); acc_u2(a0, a1, a2, a3, v1);
        acc_u2(a0, a1, a2, a3, v2); acc_u2(a0, a1, a2, a3, v3);
        j += 4;
    }
    for (; j < e; j++)
        acc_u2(a0, a1, a2, a3, __ldg(&gp[(size_t)__ldg(d_csr + j) * 32 + lane]));

    float dv = d_dinv[node];
    float4 b = __ldg((const float4*)bias + lane);
    __half2 h0 = __floats2half2_rn(fmaxf(fmaf(a0, dv, b.x), 0.f),
                                   fmaxf(fmaf(a1, dv, b.y), 0.f));
    __half2 h1 = __floats2half2_rn(fmaxf(fmaf(a2, dv, b.z), 0.f),
                                   fmaxf(fmaf(a3, dv, b.w), 0.f));
    uint2 w;
    w.x = *(unsigned*)&h0;
    w.y = *(unsigned*)&h1;
    ((uint2*)out)[(size_t)node * 32 + lane] = w;
}

// layer 3: COLS=64 -> 32 half2/row; lane covers cols {2*lane, 2*lane+1}.
// Fused min-pool (bias deferred to k_final). Same 8-deep pipeline.
__global__ void k_agg64min(const __half* __restrict__ g, int N)
{
    __shared__ unsigned sMin[64];
    int tid = threadIdx.x;
    if (tid < 64) sMin[tid] = 0xFFFFFFFFu;
    __syncthreads();

    int node = (blockIdx.x * blockDim.x + tid) >> 5;
    int lane = tid & 31;
    if (node < N) {
        const unsigned* gp = (const unsigned*)g;
        float a0 = 0.f, a1 = 0.f;
        {
            unsigned v = __ldg(&gp[(size_t)node * 32 + lane]);
            float2 f = __half22float2(*(__half2*)&v);
            a0 += f.x; a1 += f.y;
        }
        int s = d_off[node], e = d_off[node + 1];
        int j = s;
        int c0, c1, c2, c3, c4, c5, c6, c7;
        bool have = (j + 8 <= e);
        if (have) {
            c0 = __ldg(d_csr + j);     c1 = __ldg(d_csr + j + 1);
            c2 = __ldg(d_csr + j + 2); c3 = __ldg(d_csr + j + 3);
            c4 = __ldg(d_csr + j + 4); c5 = __ldg(d_csr + j + 5);
            c6 = __ldg(d_csr + j + 6); c7 = __ldg(d_csr + j + 7);
        }
        while (have) {
            bool nxt = (j + 16 <= e);
            int m0, m1, m2, m3, m4, m5, m6, m7;
            if (nxt) {
                m0 = __ldg(d_csr + j + 8);  m1 = __ldg(d_csr + j + 9);
                m2 = __ldg(d_csr + j + 10); m3 = __ldg(d_csr + j + 11);
                m4 = __ldg(d_csr + j + 12); m5 = __ldg(d_csr + j + 13);
                m6 = __ldg(d_csr + j + 14); m7 = __ldg(d_csr + j + 15);
            }
            unsigned v0 = __ldg(&gp[(size_t)c0 * 32 + lane]);
            unsigned v1 = __ldg(&gp[(size_t)c1 * 32 + lane]);
            unsigned v2 = __ldg(&gp[(size_t)c2 * 32 + lane]);
            unsigned v3 = __ldg(&gp[(size_t)c3 * 32 + lane]);
            unsigned v4 = __ldg(&gp[(size_t)c4 * 32 + lane]);
            unsigned v5 = __ldg(&gp[(size_t)c5 * 32 + lane]);
            unsigned v6 = __ldg(&gp[(size_t)c6 * 32 + lane]);
            unsigned v7 = __ldg(&gp[(size_t)c7 * 32 + lane]);
            float2 f;
            f = __half22float2(*(__half2*)&v0); a0 += f.x; a1 += f.y;
            f = __half22float2(*(__half2*)&v1); a0 += f.x; a1 += f.y;
            f = __half22float2(*(__half2*)&v2); a0 += f.x; a1 += f.y;
            f = __half22float2(*(__half2*)&v3); a0 += f.x; a1 += f.y;
            f = __half22float2(*(__half2*)&v4); a0 += f.x; a1 += f.y;
            f = __half22float2(*(__half2*)&v5); a0 += f.x; a1 += f.y;
            f = __half22float2(*(__half2*)&v6); a0 += f.x; a1 += f.y;
            f = __half22float2(*(__half2*)&v7); a0 += f.x; a1 += f.y;
            c0 = m0; c1 = m1; c2 = m2; c3 = m3;
            c4 = m4; c5 = m5; c6 = m6; c7 = m7;
            j += 8;
            have = nxt;
        }
        if (j + 4 <= e) {
            int n0 = __ldg(d_csr + j),     n1 = __ldg(d_csr + j + 1);
            int n2 = __ldg(d_csr + j + 2), n3 = __ldg(d_csr + j + 3);
            unsigned v0 = __ldg(&gp[(size_t)n0 * 32 + lane]);
            unsigned v1 = __ldg(&gp[(size_t)n1 * 32 + lane]);
            unsigned v2 = __ldg(&gp[(size_t)n2 * 32 + lane]);
            unsigned v3 = __ldg(&gp[(size_t)n3 * 32 + lane]);
            float2 f;
            f = __half22float2(*(__half2*)&v0); a0 += f.x; a1 += f.y;
            f = __half22float2(*(__half2*)&v1); a0 += f.x; a1 += f.y;
            f = __half22float2(*(__half2*)&v2); a0 += f.x; a1 += f.y;
            f = __half22float2(*(__half2*)&v3); a0 += f.x; a1 += f.y;
            j += 4;
        }
        for (; j < e; j++) {
            unsigned v = __ldg(&gp[(size_t)__ldg(d_csr + j) * 32 + lane]);
            float2 f = __half22float2(*(__half2*)&v);
            a0 += f.x; a1 += f.y;
        }
        float dv = d_dinv[node];
        atomicMin(&sMin[2 * lane + 0], enc_f(a0 * dv));
        atomicMin(&sMin[2 * lane + 1], enc_f(a1 * dv));
    }
    __syncthreads();
    if (tid < 64) atomicMin(&d_gmin[tid], sMin[tid]);
}

__global__ void k_final(const float* __restrict__ b3, float* __restrict__ out) {
    int c = threadIdx.x;
    out[c] = dec_f(d_gmin[c]) + b3[c];
}

extern "C" void kernel_launch(void* const* d_in, const int* in_sizes, int n_in,
                              void* d_out, int out_size)
{
    const float* x  = (const float*)d_in[0];
    const int*   ei = (const int*)d_in[1];
    const float* W1 = (const float*)d_in[2];
    const float* b1 = (const float*)d_in[3];
    const float* W2 = (const float*)d_in[4];
    const float* b2 = (const float*)d_in[5];
    const float* W3 = (const float*)d_in[6];
    const float* b3 = (const float*)d_in[7];
    float* out = (float*)d_out;

    int N = in_sizes[0] / 128;
    int E = in_sizes[1] / 2;
    const int* src = ei;
    const int* dst = ei + E;

    __half *B1, *B2, *G;
    cudaGetSymbolAddress((void**)&B1, d_B1);
    cudaGetSymbolAddress((void**)&B2, d_B2);
    cudaGetSymbolAddress((void**)&G, d_G);

    const int smem = (128 * (64 + 4) + 128 * 128) * 4;   // == (128*(128+4)+128*64)*4
    cudaFuncSetAttribute(k_gemm<128, 64, true,  float>,  cudaFuncAttributeMaxDynamicSharedMemorySize, smem);
    cudaFuncSetAttribute(k_gemm<128, 64, false, __half>, cudaFuncAttributeMaxDynamicSharedMemorySize, smem);
    cudaFuncSetAttribute(k_gemm<64, 128, false, __half>, cudaFuncAttributeMaxDynamicSharedMemorySize, smem);

    // CSR: hist + scans (dinv ready after scan3; cnt/cur self-cleaned there)
    k_hist<<<(E + 255) / 256, 256>>>(dst, E);
    int nblk = (N + 1023) / 1024;
    k_scan1<<<nblk, 256>>>(N);
    k_scan2<<<1, 128>>>(nblk);
    k_scan3<<<(N + 255) / 256, 256>>>(N, E);

    // Layer-1 GEMM with CSR fill fused at LOW block ids (overlaps first waves)
    const int fillBlocks = 1024;
    int gb1 = (N + 63) / 64;
    k_gemm<128, 64, true, float><<<gb1 + fillBlocks, 128, smem>>>(x, W1, G, N, src, dst, E, fillBlocks);
    k_agg128<<<(N * 32 + 255) / 256, 256>>>(G, b1, B2, N);

    // Layer 2
    k_gemm<128, 64, false, __half><<<(N + 63) / 64, 128, smem>>>(B2, W2, G, N, nullptr, nullptr, 0, 0);
    k_agg128<<<(N * 32 + 255) / 256, 256>>>(G, b2, B1, N);

    // Layer 3 (64 cols) + fused min-pool
    k_gemm<64, 128, false, __half><<<(N + 127) / 128, 128, smem>>>(B1, W3, G, N, nullptr, nullptr, 0, 0);
    k_agg64min<<<(N * 32 + 255) / 256, 256>>>(G, N);

    k_final<<<1, 64>>>(b3, out);
}

// round 10
// speedup vs baseline: 1.4906x; 1.4906x over previous
#include <cuda_runtime.h>
#include <cuda_fp16.h>

#define NMAX 100000
#define EMAX 1600000
#define CMAX 128

// Scratch (__device__ globals: allocation-free rule)
__device__ __half d_G[(size_t)NMAX * CMAX];       // messages (half)
__device__ __half d_B1[(size_t)NMAX * CMAX];      // activations (half)
__device__ __half d_B2[(size_t)NMAX * CMAX];
__device__ float  d_dinv[NMAX];
__device__ int    d_cnt[NMAX];
__device__ int    d_cur[NMAX];
__device__ int    d_off[NMAX + 1];
__device__ int    d_csr[EMAX];
__device__ int    d_blk[128];
__device__ int    d_blk2[128];
__device__ unsigned d_gmin[64];

__device__ __forceinline__ unsigned enc_f(float f) {
    unsigned u = __float_as_uint(f);
    return (u & 0x80000000u) ? ~u : (u | 0x80000000u);
}
__device__ __forceinline__ float dec_f(unsigned e) {
    unsigned u = (e & 0x80000000u) ? (e ^ 0x80000000u) : ~u ^ 0u;
    u = (e & 0x80000000u) ? (e ^ 0x80000000u) : ~e;
    return __uint_as_float(u);
}

// 4 halves (8B) from fp32 or half source row
__device__ __forceinline__ uint2 loadH4(const float* A, size_t row, int k4) {
    float4 v = __ldg((const float4*)(A + row * 128) + k4);
    __half2 h0 = __floats2half2_rn(v.x, v.y);
    __half2 h1 = __floats2half2_rn(v.z, v.w);
    uint2 r;
    r.x = *(unsigned*)&h0;
    r.y = *(unsigned*)&h1;
    return r;
}
__device__ __forceinline__ uint2 loadH4(const __half* A, size_t row, int k4) {
    return __ldg((const uint2*)(A + row * 128) + k4);
}

// ================= degree histogram =================
__global__ void k_hist(const int* __restrict__ dst, int E) {
    int i = blockIdx.x * blockDim.x + threadIdx.x;
    if (i < E) atomicAdd(&d_cnt[dst[i]], 1);
}

// ================= CSR scans =================
__global__ void k_scan1(int N) {
    __shared__ int sh[256];
    int t = threadIdx.x;
    int base = blockIdx.x * 1024 + t * 4;
    int c0 = 0, c1 = 0, c2 = 0, c3 = 0;
    if (base + 3 < N) {
        int4 v = *(const int4*)&d_cnt[base];
        c0 = v.x; c1 = v.y; c2 = v.z; c3 = v.w;
    } else {
        if (base + 0 < N) c0 = d_cnt[base + 0];
        if (base + 1 < N) c1 = d_cnt[base + 1];
        if (base + 2 < N) c2 = d_cnt[base + 2];
        if (base + 3 < N) c3 = d_cnt[base + 3];
    }
    int s = c0 + c1 + c2 + c3;
    sh[t] = s;
    __syncthreads();
    for (int d = 1; d < 256; d <<= 1) {
        int v = (t >= d) ? sh[t - d] : 0;
        __syncthreads();
        sh[t] += v;
        __syncthreads();
    }
    int excl = sh[t] - s;
    if (base + 0 < N) d_off[base + 0] = excl;
    if (base + 1 < N) d_off[base + 1] = excl + c0;
    if (base + 2 < N) d_off[base + 2] = excl + c0 + c1;
    if (base + 3 < N) d_off[base + 3] = excl + c0 + c1 + c2;
    if (t == 255) d_blk[blockIdx.x] = sh[255];
}

__global__ void k_scan2(int nblk) {
    __shared__ int sh[128];
    int t = threadIdx.x;
    int v = (t < nblk) ? d_blk[t] : 0;
    sh[t] = v;
    __syncthreads();
    for (int d = 1; d < 128; d <<= 1) {
        int u = (t >= d) ? sh[t - d] : 0;
        __syncthreads();
        sh[t] += u;
        __syncthreads();
    }
    d_blk2[t] = sh[t] - v;
}

// Also: computes dinv, zeroes d_cnt/d_cur for graph replay, inits gmin.
__global__ void k_scan3(int N, int E) {
    int i = blockIdx.x * blockDim.x + threadIdx.x;
    if (i < N) {
        d_off[i] += d_blk2[i >> 10];
        d_dinv[i] = rsqrtf((float)d_cnt[i] + 1.0f);  // +1 self-loop
        d_cnt[i] = 0;                                 // self-clean for replay
        d_cur[i] = 0;
    }
    if (i == 0) d_off[N] = E;
    if (blockIdx.x == 0 && threadIdx.x < 64) d_gmin[threadIdx.x] = 0xFFFFFFFFu;
}

// ================= tensor-core GEMM =================
// g[row] = half(dinv[row] * (A[row] @ W)); A: [N][128] (fp32 or half), W: [128][COLS] fp32.
// 256 threads; tile = 128 rows x COLS. Warp w computes rows w*16..w*16+15 via
// mma.sync.m16n8k16 (f16 in, f32 accum). Smem rows padded (272B / 144B) so the
// 8-row LDSM access pattern hits distinct banks (stride % 32 words == 4).
// FILL: blocks with bid < fillBlocks do the CSR fill instead.
template <int COLS, bool FILL, typename AT>
__global__ void __launch_bounds__(256)
k_gemm_mma(const AT* __restrict__ A, const float* __restrict__ W,
           __half* __restrict__ g, int N,
           const int* __restrict__ src, const int* __restrict__ dstp, int E, int fillBlocks)
{
    if (FILL && (int)blockIdx.x < fillBlocks) {
        for (int i = blockIdx.x * 256 + threadIdx.x; i < E; i += fillBlocks * 256) {
            int d = dstp[i];
            int p = atomicAdd(&d_cur[d], 1);
            d_csr[d_off[d] + p] = src[i];
        }
        return;
    }
    constexpr int AROW = 272;                         // bytes per A smem row (128 f16 + pad)
    constexpr int WROW = (COLS == 128) ? 272 : 144;   // bytes per W smem row
    constexpr int NT = COLS / 8;                      // n-tiles of 8

    extern __shared__ char sm[];
    char* smA = sm;                                   // [128][AROW]
    char* smW = sm + 128 * AROW;                      // [128][WROW]
    const unsigned sA = (unsigned)__cvta_generic_to_shared(smA);
    const unsigned sW = (unsigned)__cvta_generic_to_shared(smW);

    const int tid = threadIdx.x;
    const int base = (blockIdx.x - (FILL ? fillBlocks : 0)) * 128;

    // Fill A (convert to f16 if needed), rows >= N zeroed
    for (int i = tid; i < 128 * 32; i += 256) {
        int r = i >> 5, k4 = i & 31;
        int row = base + r;
        uint2 v = make_uint2(0u, 0u);
        if (row < N) v = loadH4(A, (size_t)row, k4);
        *(uint2*)(smA + r * AROW + k4 * 8) = v;
    }
    // Fill W (fp32 -> f16)
    for (int i = tid; i < 128 * COLS / 4; i += 256) {
        int r = i / (COLS / 4), n4 = i % (COLS / 4);
        float4 v = __ldg((const float4*)W + i);
        __half2 h0 = __floats2half2_rn(v.x, v.y);
        __half2 h1 = __floats2half2_rn(v.z, v.w);
        uint2 u;
        u.x = *(unsigned*)&h0;
        u.y = *(unsigned*)&h1;
        *(uint2*)(smW + r * WROW + n4 * 8) = u;
    }
    __syncthreads();

    const int warp = tid >> 5;
    const int lane = tid & 31;
    const int warprow = warp * 16;
    const int lr = lane & 7;          // row within 8x8 matrix
    const int sel = lane >> 3;        // which of the 4 matrices
    const int selLo = sel & 1;
    const int selHi = sel >> 1;

    float c[NT][4];
#pragma unroll
    for (int n = 0; n < NT; n++)
#pragma unroll
        for (int q = 0; q < 4; q++) c[n][q] = 0.f;

#pragma unroll
    for (int ks = 0; ks < 8; ks++) {
        // A fragment: rows warprow..+15, k = ks*16..+15
        unsigned a0, a1, a2, a3;
        unsigned aaddr = sA + (warprow + lr + selLo * 8) * AROW + ks * 32 + selHi * 16;
        asm volatile("ldmatrix.sync.aligned.m8n8.x4.shared.b16 {%0,%1,%2,%3}, [%4];"
                     : "=r"(a0), "=r"(a1), "=r"(a2), "=r"(a3) : "r"(aaddr));
#pragma unroll
        for (int p = 0; p < NT / 2; p++) {
            // B fragments for n-tiles 2p, 2p+1 (k x n blocks, trans load)
            unsigned b0, b1, b2, b3;
            unsigned baddr = sW + (ks * 16 + lr + selLo * 8) * WROW + p * 32 + selHi * 16;
            asm volatile("ldmatrix.sync.aligned.m8n8.x4.trans.shared.b16 {%0,%1,%2,%3}, [%4];"
                         : "=r"(b0), "=r"(b1), "=r"(b2), "=r"(b3) : "r"(baddr));
            asm volatile("mma.sync.aligned.m16n8k16.row.col.f32.f16.f16.f32 "
                         "{%0,%1,%2,%3}, {%4,%5,%6,%7}, {%8,%9}, {%0,%1,%2,%3};"
                         : "+f"(c[2 * p][0]), "+f"(c[2 * p][1]), "+f"(c[2 * p][2]), "+f"(c[2 * p][3])
                         : "r"(a0), "r"(a1), "r"(a2), "r"(a3), "r"(b0), "r"(b1));
            asm volatile("mma.sync.aligned.m16n8k16.row.col.f32.f16.f16.f32 "
                         "{%0,%1,%2,%3}, {%4,%5,%6,%7}, {%8,%9}, {%0,%1,%2,%3};"
                         : "+f"(c[2 * p + 1][0]), "+f"(c[2 * p + 1][1]), "+f"(c[2 * p + 1][2]), "+f"(c[2 * p + 1][3])
                         : "r"(a0), "r"(a1), "r"(a2), "r"(a3), "r"(b2), "r"(b3));
        }
    }

    // Epilogue: scale by dinv, store half messages
    const int gq = lane >> 2;         // row group 0..7
    const int tig = lane & 3;         // col pair within n-tile
    int row0 = base + warprow + gq;
    int row1 = row0 + 8;
    float dv0 = (row0 < N) ? d_dinv[row0] : 0.f;
    float dv1 = (row1 < N) ? d_dinv[row1] : 0.f;
#pragma unroll
    for (int n = 0; n < NT; n++) {
        int col = n * 8 + 2 * tig;
        if (row0 < N) {
            __half2 h = __floats2half2_rn(c[n][0] * dv0, c[n][1] * dv0);
            *(__half2*)(g + (size_t)row0 * COLS + col) = h;
        }
        if (row1 < N) {
            __half2 h = __floats2half2_rn(c[n][2] * dv1, c[n][3] * dv1);
            *(__half2*)(g + (size_t)row1 * COLS + col) = h;
        }
    }
}

// ================= CSR aggregate (half msgs, fp32 accum, 1 warp/node) ============
__device__ __forceinline__ void acc_u2(float& a0, float& a1, float& a2, float& a3, uint2 v) {
    float2 f0 = __half22float2(*(__half2*)&v.x);
    float2 f1 = __half22float2(*(__half2*)&v.y);
    a0 += f0.x; a1 += f0.y; a2 += f1.x; a3 += f1.y;
}

__global__ void k_agg128(const __half* __restrict__ g, const float* __restrict__ bias,
                         __half* __restrict__ out, int N)
{
    int node = (blockIdx.x * blockDim.x + threadIdx.x) >> 5;
    int lane = threadIdx.x & 31;
    if (node >= N) return;
    const uint2* gp = (const uint2*)g;

    float a0 = 0.f, a1 = 0.f, a2 = 0.f, a3 = 0.f;
    acc_u2(a0, a1, a2, a3, __ldg(&gp[(size_t)node * 32 + lane]));   // self-loop
    int s = d_off[node], e = d_off[node + 1];
    int j = s;
    int c0, c1, c2, c3, c4, c5, c6, c7;
    bool have = (j + 8 <= e);
    if (have) {
        c0 = __ldg(d_csr + j);     c1 = __ldg(d_csr + j + 1);
        c2 = __ldg(d_csr + j + 2); c3 = __ldg(d_csr + j + 3);
        c4 = __ldg(d_csr + j + 4); c5 = __ldg(d_csr + j + 5);
        c6 = __ldg(d_csr + j + 6); c7 = __ldg(d_csr + j + 7);
    }
    while (have) {
        bool nxt = (j + 16 <= e);
        int m0, m1, m2, m3, m4, m5, m6, m7;
        if (nxt) {
            m0 = __ldg(d_csr + j + 8);  m1 = __ldg(d_csr + j + 9);
            m2 = __ldg(d_csr + j + 10); m3 = __ldg(d_csr + j + 11);
            m4 = __ldg(d_csr + j + 12); m5 = __ldg(d_csr + j + 13);
            m6 = __ldg(d_csr + j + 14); m7 = __ldg(d_csr + j + 15);
        }
        uint2 v0 = __ldg(&gp[(size_t)c0 * 32 + lane]);
        uint2 v1 = __ldg(&gp[(size_t)c1 * 32 + lane]);
        uint2 v2 = __ldg(&gp[(size_t)c2 * 32 + lane]);
        uint2 v3 = __ldg(&gp[(size_t)c3 * 32 + lane]);
        uint2 v4 = __ldg(&gp[(size_t)c4 * 32 + lane]);
        uint2 v5 = __ldg(&gp[(size_t)c5 * 32 + lane]);
        uint2 v6 = __ldg(&gp[(size_t)c6 * 32 + lane]);
        uint2 v7 = __ldg(&gp[(size_t)c7 * 32 + lane]);
        acc_u2(a0, a1, a2, a3, v0); acc_u2(a0, a1, a2, a3, v1);
        acc_u2(a0, a1, a2, a3, v2); acc_u2(a0, a1, a2, a3, v3);
        acc_u2(a0, a1, a2, a3, v4); acc_u2(a0, a1, a2, a3, v5);
        acc_u2(a0, a1, a2, a3, v6); acc_u2(a0, a1, a2, a3, v7);
        c0 = m0; c1 = m1; c2 = m2; c3 = m3;
        c4 = m4; c5 = m5; c6 = m6; c7 = m7;
        j += 8;
        have = nxt;
    }
    if (j + 4 <= e) {
        int n0 = __ldg(d_csr + j),     n1 = __ldg(d_csr + j + 1);
        int n2 = __ldg(d_csr + j + 2), n3 = __ldg(d_csr + j + 3);
        uint2 v0 = __ldg(&gp[(size_t)n0 * 32 + lane]);
        uint2 v1 = __ldg(&gp[(size_t)n1 * 32 + lane]);
        uint2 v2 = __ldg(&gp[(size_t)n2 * 32 + lane]);
        uint2 v3 = __ldg(&gp[(size_t)n3 * 32 + lane]);
        acc_u2(a0, a1, a2, a3, v0); acc_u2(a0, a1, a2, a3, v1);
        acc_u2(a0, a1, a2, a3, v2); acc_u2(a0, a1, a2, a3, v3);
        j += 4;
    }
    for (; j < e; j++)
        acc_u2(a0, a1, a2, a3, __ldg(&gp[(size_t)__ldg(d_csr + j) * 32 + lane]));

    float dv = d_dinv[node];
    float4 b = __ldg((const float4*)bias + lane);
    __half2 h0 = __floats2half2_rn(fmaxf(fmaf(a0, dv, b.x), 0.f),
                                   fmaxf(fmaf(a1, dv, b.y), 0.f));
    __half2 h1 = __floats2half2_rn(fmaxf(fmaf(a2, dv, b.z), 0.f),
                                   fmaxf(fmaf(a3, dv, b.w), 0.f));
    uint2 w;
    w.x = *(unsigned*)&h0;
    w.y = *(unsigned*)&h1;
    ((uint2*)out)[(size_t)node * 32 + lane] = w;
}

// layer 3: COLS=64 -> 32 half2/row; fused min-pool (bias deferred to k_final).
__global__ void k_agg64min(const __half* __restrict__ g, int N)
{
    __shared__ unsigned sMin[64];
    int tid = threadIdx.x;
    if (tid < 64) sMin[tid] = 0xFFFFFFFFu;
    __syncthreads();

    int node = (blockIdx.x * blockDim.x + tid) >> 5;
    int lane = tid & 31;
    if (node < N) {
        const unsigned* gp = (const unsigned*)g;
        float a0 = 0.f, a1 = 0.f;
        {
            unsigned v = __ldg(&gp[(size_t)node * 32 + lane]);
            float2 f = __half22float2(*(__half2*)&v);
            a0 += f.x; a1 += f.y;
        }
        int s = d_off[node], e = d_off[node + 1];
        int j = s;
        int c0, c1, c2, c3, c4, c5, c6, c7;
        bool have = (j + 8 <= e);
        if (have) {
            c0 = __ldg(d_csr + j);     c1 = __ldg(d_csr + j + 1);
            c2 = __ldg(d_csr + j + 2); c3 = __ldg(d_csr + j + 3);
            c4 = __ldg(d_csr + j + 4); c5 = __ldg(d_csr + j + 5);
            c6 = __ldg(d_csr + j + 6); c7 = __ldg(d_csr + j + 7);
        }
        while (have) {
            bool nxt = (j + 16 <= e);
            int m0, m1, m2, m3, m4, m5, m6, m7;
            if (nxt) {
                m0 = __ldg(d_csr + j + 8);  m1 = __ldg(d_csr + j + 9);
                m2 = __ldg(d_csr + j + 10); m3 = __ldg(d_csr + j + 11);
                m4 = __ldg(d_csr + j + 12); m5 = __ldg(d_csr + j + 13);
                m6 = __ldg(d_csr + j + 14); m7 = __ldg(d_csr + j + 15);
            }
            unsigned v0 = __ldg(&gp[(size_t)c0 * 32 + lane]);
            unsigned v1 = __ldg(&gp[(size_t)c1 * 32 + lane]);
            unsigned v2 = __ldg(&gp[(size_t)c2 * 32 + lane]);
            unsigned v3 = __ldg(&gp[(size_t)c3 * 32 + lane]);
            unsigned v4 = __ldg(&gp[(size_t)c4 * 32 + lane]);
            unsigned v5 = __ldg(&gp[(size_t)c5 * 32 + lane]);
            unsigned v6 = __ldg(&gp[(size_t)c6 * 32 + lane]);
            unsigned v7 = __ldg(&gp[(size_t)c7 * 32 + lane]);
            float2 f;
            f = __half22float2(*(__half2*)&v0); a0 += f.x; a1 += f.y;
            f = __half22float2(*(__half2*)&v1); a0 += f.x; a1 += f.y;
            f = __half22float2(*(__half2*)&v2); a0 += f.x; a1 += f.y;
            f = __half22float2(*(__half2*)&v3); a0 += f.x; a1 += f.y;
            f = __half22float2(*(__half2*)&v4); a0 += f.x; a1 += f.y;
            f = __half22float2(*(__half2*)&v5); a0 += f.x; a1 += f.y;
            f = __half22float2(*(__half2*)&v6); a0 += f.x; a1 += f.y;
            f = __half22float2(*(__half2*)&v7); a0 += f.x; a1 += f.y;
            c0 = m0; c1 = m1; c2 = m2; c3 = m3;
            c4 = m4; c5 = m5; c6 = m6; c7 = m7;
            j += 8;
            have = nxt;
        }
        if (j + 4 <= e) {
            int n0 = __ldg(d_csr + j),     n1 = __ldg(d_csr + j + 1);
            int n2 = __ldg(d_csr + j + 2), n3 = __ldg(d_csr + j + 3);
            unsigned v0 = __ldg(&gp[(size_t)n0 * 32 + lane]);
            unsigned v1 = __ldg(&gp[(size_t)n1 * 32 + lane]);
            unsigned v2 = __ldg(&gp[(size_t)n2 * 32 + lane]);
            unsigned v3 = __ldg(&gp[(size_t)n3 * 32 + lane]);
            float2 f;
            f = __half22float2(*(__half2*)&v0); a0 += f.x; a1 += f.y;
            f = __half22float2(*(__half2*)&v1); a0 += f.x; a1 += f.y;
            f = __half22float2(*(__half2*)&v2); a0 += f.x; a1 += f.y;
            f = __half22float2(*(__half2*)&v3); a0 += f.x; a1 += f.y;
            j += 4;
        }
        for (; j < e; j++) {
            unsigned v = __ldg(&gp[(size_t)__ldg(d_csr + j) * 32 + lane]);
            float2 f = __half22float2(*(__half2*)&v);
            a0 += f.x; a1 += f.y;
        }
        float dv = d_dinv[node];
        atomicMin(&sMin[2 * lane + 0], enc_f(a0 * dv));
        atomicMin(&sMin[2 * lane + 1], enc_f(a1 * dv));
    }
    __syncthreads();
    if (tid < 64) atomicMin(&d_gmin[tid], sMin[tid]);
}

__global__ void k_final(const float* __restrict__ b3, float* __restrict__ out) {
    int c = threadIdx.x;
    out[c] = dec_f(d_gmin[c]) + b3[c];
}

extern "C" void kernel_launch(void* const* d_in, const int* in_sizes, int n_in,
                              void* d_out, int out_size)
{
    const float* x  = (const float*)d_in[0];
    const int*   ei = (const int*)d_in[1];
    const float* W1 = (const float*)d_in[2];
    const float* b1 = (const float*)d_in[3];
    const float* W2 = (const float*)d_in[4];
    const float* b2 = (const float*)d_in[5];
    const float* W3 = (const float*)d_in[6];
    const float* b3 = (const float*)d_in[7];
    float* out = (float*)d_out;

    int N = in_sizes[0] / 128;
    int E = in_sizes[1] / 2;
    const int* src = ei;
    const int* dst = ei + E;

    __half *B1, *B2, *G;
    cudaGetSymbolAddress((void**)&B1, d_B1);
    cudaGetSymbolAddress((void**)&B2, d_B2);
    cudaGetSymbolAddress((void**)&G, d_G);

    const int smem128 = 128 * 272 + 128 * 272;   // 69632
    const int smem64  = 128 * 272 + 128 * 144;   // 53248
    cudaFuncSetAttribute(k_gemm_mma<128, true,  float>,  cudaFuncAttributeMaxDynamicSharedMemorySize, smem128);
    cudaFuncSetAttribute(k_gemm_mma<128, false, __half>, cudaFuncAttributeMaxDynamicSharedMemorySize, smem128);
    cudaFuncSetAttribute(k_gemm_mma<64,  false, __half>, cudaFuncAttributeMaxDynamicSharedMemorySize, smem64);

    // CSR: hist + scans (dinv ready after scan3; cnt/cur self-cleaned there)
    k_hist<<<(E + 255) / 256, 256>>>(dst, E);
    int nblk = (N + 1023) / 1024;
    k_scan1<<<nblk, 256>>>(N);
    k_scan2<<<1, 128>>>(nblk);
    k_scan3<<<(N + 255) / 256, 256>>>(N, E);

    int gb = (N + 127) / 128;
    const int fillBlocks = 512;

    // Layer 1: tensor GEMM (x @ W1 -> G) with CSR fill fused at low block ids
    k_gemm_mma<128, true, float><<<gb + fillBlocks, 256, smem128>>>(x, W1, G, N, src, dst, E, fillBlocks);
    k_agg128<<<(N * 32 + 255) / 256, 256>>>(G, b1, B2, N);

    // Layer 2
    k_gemm_mma<128, false, __half><<<gb, 256, smem128>>>(B2, W2, G, N, nullptr, nullptr, 0, 0);
    k_agg128<<<(N * 32 + 255) / 256, 256>>>(G, b2, B1, N);

    // Layer 3 (64 cols) + fused min-pool
    k_gemm_mma<64, false, __half><<<gb, 256, smem64>>>(B1, W3, G, N, nullptr, nullptr, 0, 0);
    k_agg64min<<<(N * 32 + 255) / 256, 256>>>(G, N);

    k_final<<<1, 64>>>(b3, out);
}